// round 16
// baseline (speedup 1.0000x reference)
#include <cuda_runtime.h>
#include <cstdint>

// ============================ constants ============================
#define NR        200               // number of masks
#define HW        200704            // 448*448 = 6272 * 32
#define NWORDS    6272              // packed u32 words per mask
#define TOTW      (NR*NWORDS)       // 1254400 total words
#define GRID      148
#define NTHREADS  1024
#define NWARPS    (GRID*32)         // 4736 warps grid-wide
#define MAXPAIRS  19900

__device__ uint32_t g_packed[TOTW];          // 5.02 MB packed bitmasks (L2-resident)
__device__ float    g_sums[NR];              // per-mask areas
__device__ float    g_inter[NR * NR];        // only same-label upper-tri entries written/read
__device__ float    g_comp[256];
__device__ int2     g_pairs[MAXPAIRS];
__device__ int      g_npairs;
__device__ unsigned g_count;
__device__ unsigned g_gen;

// grid barrier: atomic arrivals, plain-load polling with nanosleep backoff (proven)
__device__ __forceinline__ void grid_barrier() {
    __syncthreads();
    if (threadIdx.x == 0) {
        __threadfence();
        unsigned gen = *(volatile unsigned*)&g_gen;
        unsigned arrived = atomicAdd(&g_count, 1u) + 1u;
        if (arrived == GRID) {
            atomicExch(&g_count, 0u);
            __threadfence();
            atomicAdd(&g_gen, 1u);
        } else {
            while (*(volatile unsigned*)&g_gen == gen) __nanosleep(128);
        }
        __threadfence();
    }
    __syncthreads();
}

// ============================ fused kernel ============================
__global__ __launch_bounds__(NTHREADS, 1)
void fused_kernel(const float* __restrict__ seg,
                  const float* __restrict__ scores,
                  const int* __restrict__ labels,
                  float* __restrict__ out) {
    const int tid = threadIdx.x;
    const int wid = tid >> 5;
    const int lid = tid & 31;
    const int bid = blockIdx.x;
    const int gw  = bid * 32 + wid;           // global warp id, 0..4735
    const int gtid = bid * NTHREADS + tid;    // global thread id

    // reset per-run state (consumed only after barrier #1)
    if (bid == 0 && tid == 0) g_npairs = 0;

    // ================= phase 1: pack masks to bits (HBM-bound streaming) =================
    // word w covers seg[mask*HW + word*32 .. +31]; warp reads 128B coalesced, ballot, store.
    {
        #pragma unroll 4
        for (int w = gw; w < TOTW; w += NWARPS) {
            const int mask = w / NWORDS;
            const int word = w - mask * NWORDS;
            const float v = __ldg(seg + (size_t)mask * HW + (size_t)word * 32 + lid);
            const unsigned bits = __ballot_sync(~0u, v > 0.5f);
            if (lid == 0) g_packed[w] = bits;
        }
    }

    grid_barrier();

    // ================= phase 2a: per-mask areas via popcount (warps 0..199) =================
    {
        const int m = gw;
        if (m < NR) {
            const uint32_t* p = g_packed + (size_t)m * NWORDS;
            int s = 0;
            #pragma unroll 7
            for (int k = lid; k < NWORDS; k += 32) s += __popc(p[k]);
            #pragma unroll
            for (int o = 16; o; o >>= 1) s += __shfl_xor_sync(~0u, s, o);
            if (lid == 0) g_sums[m] = (float)s;
        }
    }

    // ================= phase 2b: build same-label pair list =================
    {
        for (int c = gtid; c < NR * NR; c += GRID * NTHREADS) {
            const int i = c / NR, j = c - i * NR;
            if (i < j && labels[i] == labels[j]) {
                const int slot = atomicAdd(&g_npairs, 1);
                g_pairs[slot] = make_int2(i, j);
            }
        }
    }

    grid_barrier();

    // ================= phase 3: pair intersections via AND+POPC (warp per pair) =================
    {
        const int np = *(volatile int*)&g_npairs;
        for (int k = gw; k < np; k += NWARPS) {
            const int2 pr = g_pairs[k];
            const uint32_t* pa = g_packed + (size_t)pr.x * NWORDS;
            const uint32_t* pb = g_packed + (size_t)pr.y * NWORDS;
            int s = 0;
            #pragma unroll 7
            for (int w = lid; w < NWORDS; w += 32)
                s += __popc(pa[w] & pb[w]);
            #pragma unroll
            for (int o = 16; o; o >>= 1) s += __shfl_xor_sync(~0u, s, o);
            if (lid == 0) g_inter[pr.x * NR + pr.y] = (float)s;
        }
    }

    grid_barrier();

    // ================= phase 4a: compensate IoU, one warp per j =================
    {
        const int j = gw;
        if (j < NR) {
            const int lj = labels[j];
            const float sj = g_sums[j];
            float m = 0.f;
            for (int i = lid; i < j; i += 32) {
                if (labels[i] == lj) {
                    const float in_ = g_inter[i * NR + j];
                    m = fmaxf(m, in_ / (g_sums[i] + sj - in_));
                }
            }
            #pragma unroll
            for (int o = 16; o; o >>= 1) m = fmaxf(m, __shfl_xor_sync(~0u, m, o));
            if (lid == 0) g_comp[j] = m;
        }
    }

    grid_barrier();

    // ================= phase 4b: decay coefficient (min over ALL i), exact jnp semantics =================
    {
        const int j = gw;
        if (j < NR) {
            const int lj = labels[j];
            const float sj = g_sums[j];
            float mn = 3.4e38f;
            for (int i = lid; i < NR; i += 32) {
                float d = 0.f;
                if (i < j && labels[i] == lj) {
                    const float in_ = g_inter[i * NR + j];
                    d = in_ / (g_sums[i] + sj - in_);
                }
                const float c = g_comp[i];
                mn = fminf(mn, c * c - d * d);
            }
            #pragma unroll
            for (int o = 16; o; o >>= 1) mn = fminf(mn, __shfl_xor_sync(~0u, mn, o));
            if (lid == 0) out[j] = scores[j] * expf(2.0f * mn);   // SIGMA = 2
        }
    }
}

// ============================ launch ============================
extern "C" void kernel_launch(void* const* d_in, const int* in_sizes, int n_in,
                              void* d_out, int out_size) {
    const float* seg    = (const float*)d_in[0];
    const float* scores = (const float*)d_in[1];
    const int*   labels = (const int*)d_in[2];
    float* out = (float*)d_out;

    fused_kernel<<<GRID, NTHREADS>>>(seg, scores, labels, out);
}

// round 17
// speedup vs baseline: 1.5552x; 1.5552x over previous
#include <cuda_runtime.h>
#include <cstdint>

// ============================ constants ============================
#define NR        200               // number of masks
#define HW        200704            // 448*448 = 6272 * 32
#define NWORDS    6272              // packed u32 words per mask
#define TOTW      (NR*NWORDS)       // 1254400 total words
#define GRID      148
#define NTHREADS  1024
#define NTOT      (GRID*NTHREADS)   // 151552 threads
#define NWARPS    (GRID*32)
#define MAXPAIRS  19900

__device__ uint32_t g_packed[TOTW];          // 5.02 MB packed bitmasks (L2-resident)
__device__ float    g_sums[NR];
__device__ float    g_inter[NR * NR];        // only same-label upper-tri entries written/read
__device__ float    g_comp[256];
__device__ int2     g_pairs[MAXPAIRS];
__device__ int      g_npairs;
__device__ unsigned g_count;
__device__ unsigned g_gen;

// grid barrier: atomic arrivals, plain-load polling with nanosleep backoff (proven)
__device__ __forceinline__ void grid_barrier() {
    __syncthreads();
    if (threadIdx.x == 0) {
        __threadfence();
        unsigned gen = *(volatile unsigned*)&g_gen;
        unsigned arrived = atomicAdd(&g_count, 1u) + 1u;
        if (arrived == GRID) {
            atomicExch(&g_count, 0u);
            __threadfence();
            atomicAdd(&g_gen, 1u);
        } else {
            while (*(volatile unsigned*)&g_gen == gen) __nanosleep(128);
        }
        __threadfence();
    }
    __syncthreads();
}

// pack one word: 32 consecutive pixels starting at p (16B-aligned), thread-local
__device__ __forceinline__ uint32_t pack_word(const float4* __restrict__ p) {
    uint32_t bits = 0;
    #pragma unroll
    for (int j = 0; j < 8; j++) {
        const float4 v = __ldg(p + j);
        bits |= (v.x > 0.5f ? (1u << (4 * j + 0)) : 0u);
        bits |= (v.y > 0.5f ? (1u << (4 * j + 1)) : 0u);
        bits |= (v.z > 0.5f ? (1u << (4 * j + 2)) : 0u);
        bits |= (v.w > 0.5f ? (1u << (4 * j + 3)) : 0u);
    }
    return bits;
}

// ============================ fused kernel ============================
__global__ __launch_bounds__(NTHREADS, 1)
void fused_kernel(const float* __restrict__ seg,
                  const float* __restrict__ scores,
                  const int* __restrict__ labels,
                  float* __restrict__ out) {
    const int tid = threadIdx.x;
    const int wid = tid >> 5;
    const int lid = tid & 31;
    const int bid = blockIdx.x;
    const int gw  = bid * 32 + wid;
    const int gtid = bid * NTHREADS + tid;

    if (bid == 0 && tid == 0) g_npairs = 0;

    // ================= phase 1: pack masks to bits (thread-local, MLP-rich) =================
    // TOTW = 1254400 = 151552*8 + 41984. Each thread packs 8 or 9 words; word w reads
    // 32 consecutive floats. Consecutive gtid -> consecutive w (coalesced stores; loads
    // cover contiguous 4KB per warp per step).
    {
        // steady 8 words per thread
        #pragma unroll
        for (int it = 0; it < 8; it++) {
            const int w = gtid + it * NTOT;
            const int mask = w / NWORDS;
            const int word = w - mask * NWORDS;
            const float4* p = reinterpret_cast<const float4*>(
                seg + (size_t)mask * HW + (size_t)word * 32);
            g_packed[w] = pack_word(p);
        }
        // tail
        const int w = gtid + 8 * NTOT;
        if (w < TOTW) {
            const int mask = w / NWORDS;
            const int word = w - mask * NWORDS;
            const float4* p = reinterpret_cast<const float4*>(
                seg + (size_t)mask * HW + (size_t)word * 32);
            g_packed[w] = pack_word(p);
        }
    }

    grid_barrier();

    // ================= phase 2a: per-mask areas via popcount (warps 0..199) =================
    {
        const int m = gw;
        if (m < NR) {
            const uint32_t* p = g_packed + (size_t)m * NWORDS;
            int s = 0;
            #pragma unroll 7
            for (int k = lid; k < NWORDS; k += 32) s += __popc(__ldg(p + k));
            #pragma unroll
            for (int o = 16; o; o >>= 1) s += __shfl_xor_sync(~0u, s, o);
            if (lid == 0) g_sums[m] = (float)s;
        }
    }

    // ================= phase 2b: build same-label pair list =================
    {
        for (int c = gtid; c < NR * NR; c += NTOT) {
            const int i = c / NR, j = c - i * NR;
            if (i < j && labels[i] == labels[j]) {
                const int slot = atomicAdd(&g_npairs, 1);
                g_pairs[slot] = make_int2(i, j);
            }
        }
    }

    grid_barrier();

    // ================= phase 3: pair intersections via AND+POPC (warp per pair) =================
    {
        const int np = *(volatile int*)&g_npairs;
        for (int k = gw; k < np; k += NWARPS) {
            const int2 pr = g_pairs[k];
            const uint32_t* pa = g_packed + (size_t)pr.x * NWORDS;
            const uint32_t* pb = g_packed + (size_t)pr.y * NWORDS;
            int s = 0;
            #pragma unroll 7
            for (int w = lid; w < NWORDS; w += 32)
                s += __popc(__ldg(pa + w) & __ldg(pb + w));
            #pragma unroll
            for (int o = 16; o; o >>= 1) s += __shfl_xor_sync(~0u, s, o);
            if (lid == 0) g_inter[pr.x * NR + pr.y] = (float)s;
        }
    }

    grid_barrier();

    // ================= phase 4a: compensate IoU, one warp per j =================
    {
        const int j = gw;
        if (j < NR) {
            const int lj = labels[j];
            const float sj = g_sums[j];
            float m = 0.f;
            for (int i = lid; i < j; i += 32) {
                if (labels[i] == lj) {
                    const float in_ = g_inter[i * NR + j];
                    m = fmaxf(m, in_ / (g_sums[i] + sj - in_));
                }
            }
            #pragma unroll
            for (int o = 16; o; o >>= 1) m = fmaxf(m, __shfl_xor_sync(~0u, m, o));
            if (lid == 0) g_comp[j] = m;
        }
    }

    grid_barrier();

    // ================= phase 4b: decay coefficient (min over ALL i), exact jnp semantics =================
    {
        const int j = gw;
        if (j < NR) {
            const int lj = labels[j];
            const float sj = g_sums[j];
            float mn = 3.4e38f;
            for (int i = lid; i < NR; i += 32) {
                float d = 0.f;
                if (i < j && labels[i] == lj) {
                    const float in_ = g_inter[i * NR + j];
                    d = in_ / (g_sums[i] + sj - in_);
                }
                const float c = g_comp[i];
                mn = fminf(mn, c * c - d * d);
            }
            #pragma unroll
            for (int o = 16; o; o >>= 1) mn = fminf(mn, __shfl_xor_sync(~0u, mn, o));
            if (lid == 0) out[j] = scores[j] * expf(2.0f * mn);   // SIGMA = 2
        }
    }
}

// ============================ launch ============================
extern "C" void kernel_launch(void* const* d_in, const int* in_sizes, int n_in,
                              void* d_out, int out_size) {
    const float* seg    = (const float*)d_in[0];
    const float* scores = (const float*)d_in[1];
    const int*   labels = (const int*)d_in[2];
    float* out = (float*)d_out;

    fused_kernel<<<GRID, NTHREADS>>>(seg, scores, labels, out);
}